// round 16
// baseline (speedup 1.0000x reference)
#include <cuda_runtime.h>
#include <cstdint>

// QuantizedEmbedding FINAL (= R11): full-TMA warp-autonomous pipeline.
// Converged optimum after exhausting the {read x write} path matrix:
//   - TMA bulk stores are the critical lever (L2 38% vs 61% with STG; -12us)
//   - per warp: 2x1KB bulk reads (own mbarriers) + 2x2KB bulk stores
//     (bulk_group, wait_group 1), all scales prefetched, store-drain ordered
//     before read-wait, no CTA-wide barriers in the loop.
// DRAM pinned at ~67% / 5.36 TB/s = mixed gather-read/stream-write ceiling.

static constexpr int PACKED   = 2048;    // packed int32 per row (8KB)
static constexpr int NGROUPS  = 128;
static constexpr int DIM      = 4096;
static constexpr int THREADS  = 256;
static constexpr int WARPS    = THREADS / 32;          // 8
static constexpr int TOKS     = 4;                      // tokens per CTA
static constexpr int IN_P     = PACKED / WARPS;         // 256 int32 = 1KB per warp slice
static constexpr int IN_B     = IN_P * 4;               // 1024 B
static constexpr int SLICE_F  = DIM / WARPS;            // 512 floats = 2KB out slice
static constexpr int SLICE_B  = SLICE_F * 4;            // 2048 B
static constexpr int SMEM_IN    = 0;                               // 8*2*1KB = 16KB
static constexpr int SMEM_OUT   = WARPS * 2 * IN_B;                // 16384
static constexpr int SMEM_MBAR  = SMEM_OUT + WARPS * 2 * SLICE_B;  // 49152
static constexpr int SMEM_BYTES = SMEM_MBAR + WARPS * 2 * 8 + 64;

__device__ __forceinline__ float4 dq2(int a, int b, float s) {
    float4 r;
    r.x = (float)(a / 16 - 8) * s;       // trunc-toward-zero high nibble
    r.y = (float)((a & 15) - 8) * s;     // nonneg mod-16 low nibble
    r.z = (float)(b / 16 - 8) * s;
    r.w = (float)((b & 15) - 8) * s;
    return r;
}

__device__ __forceinline__ void mbar_wait(uint32_t mbar, uint32_t parity) {
    asm volatile(
        "{\n\t"
        ".reg .pred P;\n\t"
        "WL_%=:\n\t"
        "mbarrier.try_wait.parity.acquire.cta.shared::cta.b64 P, [%0], %1, 0x989680;\n\t"
        "@P bra.uni WD_%=;\n\t"
        "bra.uni WL_%=;\n\t"
        "WD_%=:\n\t"
        "}"
        :: "r"(mbar), "r"(parity) : "memory");
}

__device__ __forceinline__ void issue_read(uint32_t dst, const int* src, uint32_t mbar) {
    asm volatile("mbarrier.arrive.expect_tx.shared.b64 _, [%0], %1;"
                 :: "r"(mbar), "n"(IN_B) : "memory");
    asm volatile("cp.async.bulk.shared::cta.global.mbarrier::complete_tx::bytes "
                 "[%0], [%1], %2, [%3];"
                 :: "r"(dst), "l"(src), "n"(IN_B), "r"(mbar) : "memory");
}

__global__ void __launch_bounds__(THREADS)
qemb_kernel(const int* __restrict__ indices,
            const int* __restrict__ weight,
            const float* __restrict__ scales,
            float* __restrict__ out,
            int n_tokens)
{
    extern __shared__ __align__(128) unsigned char smem[];
    uint32_t sbase = (uint32_t)__cvta_generic_to_shared(smem);

    int t    = threadIdx.x;
    int warp = t >> 5;
    int lane = t & 31;
    long base = (long)blockIdx.x * TOKS;   // 16384 = 4096*4, exact

    uint32_t in0  = sbase + SMEM_IN  + warp * 2 * IN_B;      // [2][1KB]
    uint32_t out0 = sbase + SMEM_OUT + warp * 2 * SLICE_B;   // [2][2KB]
    uint32_t mb0  = sbase + SMEM_MBAR + warp * 16;           // 2 mbarriers

    if (lane == 0) {
        asm volatile("mbarrier.init.shared.b64 [%0], 1;" :: "r"(mb0)     : "memory");
        asm volatile("mbarrier.init.shared.b64 [%0], 1;" :: "r"(mb0 + 8) : "memory");
        asm volatile("fence.proxy.async.shared::cta;" ::: "memory");
    }
    __syncwarp();

    int4 idx4 = __ldg(reinterpret_cast<const int4*>(indices + base));
    int idxs[TOKS] = { idx4.x, idx4.y, idx4.z, idx4.w };

    int goff = warp * 16 + (lane >> 1);   // scale group for this thread

    // prologue: issue read of token 0; prefetch ALL 4 scales (independent)
    if (lane == 0)
        issue_read(in0, weight + (long)idxs[0] * PACKED + warp * IN_P, mb0);
    float sc[TOKS];
    #pragma unroll
    for (int j = 0; j < TOKS; j++)
        sc[j] = __ldg(scales + (long)idxs[j] * NGROUPS + goff);

    #pragma unroll
    for (int i = 0; i < TOKS; i++) {
        int k = i & 1;

        // issue read for token i+1 into the other buffer (consumed at i-1)
        if (i + 1 < TOKS && lane == 0) {
            uint32_t kn = (i + 1) & 1;
            issue_read(in0 + kn * IN_B,
                       weight + (long)idxs[i + 1] * PACKED + warp * IN_P,
                       mb0 + kn * 8);
        }

        // out-buffer k drain guard FIRST (overlaps with the read wait below)
        if (i >= 2 && lane == 0)
            asm volatile("cp.async.bulk.wait_group %0;" :: "n"(1) : "memory");

        // wait for token i's input slice: parity flips every 2 uses
        mbar_wait(mb0 + k * 8, (i >> 1) & 1);

        uint32_t a0 = in0 + k * IN_B + lane * 32;
        int4 w0, w1;
        asm volatile("ld.shared.v4.u32 {%0,%1,%2,%3}, [%4];"
                     : "=r"(w0.x), "=r"(w0.y), "=r"(w0.z), "=r"(w0.w) : "r"(a0));
        asm volatile("ld.shared.v4.u32 {%0,%1,%2,%3}, [%4];"
                     : "=r"(w1.x), "=r"(w1.y), "=r"(w1.z), "=r"(w1.w) : "r"(a0 + 16));
        __syncwarp();   // all lanes past wait_group point before STS into buffer k

        float s = sc[i];
        float4* bp = reinterpret_cast<float4*>(smem + SMEM_OUT
                       + warp * 2 * SLICE_B + k * SLICE_B) + lane * 4;
        bp[0] = dq2(w0.x, w0.y, s);
        bp[1] = dq2(w0.z, w0.w, s);
        bp[2] = dq2(w1.x, w1.y, s);
        bp[3] = dq2(w1.z, w1.w, s);

        asm volatile("fence.proxy.async.shared::cta;" ::: "memory");
        __syncwarp();

        if (lane == 0) {
            void* g = (void*)(out + (base + i) * DIM + warp * SLICE_F);
            asm volatile("cp.async.bulk.global.shared::cta.bulk_group [%0], [%1], %2;"
                         :: "l"(g), "r"(out0 + k * SLICE_B), "n"(SLICE_B) : "memory");
            asm volatile("cp.async.bulk.commit_group;" ::: "memory");
        }
    }

    if (lane == 0)
        asm volatile("cp.async.bulk.wait_group 0;" ::: "memory");
}

extern "C" void kernel_launch(void* const* d_in, const int* in_sizes, int n_in,
                              void* d_out, int out_size)
{
    const int*   indices = (const int*)d_in[0];
    const int*   weight  = (const int*)d_in[1];
    const float* scales  = (const float*)d_in[2];
    float*       out     = (float*)d_out;

    int n_tokens = in_sizes[0];  // 16384

    cudaFuncSetAttribute(qemb_kernel,
                         cudaFuncAttributeMaxDynamicSharedMemorySize, SMEM_BYTES);
    cudaFuncSetAttribute(qemb_kernel,
                         cudaFuncAttributePreferredSharedMemoryCarveout, 100);

    int grid = n_tokens / TOKS;  // 4096
    qemb_kernel<<<grid, THREADS, SMEM_BYTES>>>(indices, weight, scales, out, n_tokens);
}

// round 17
// speedup vs baseline: 1.3910x; 1.3910x over previous
#include <cuda_runtime.h>
#include <cstdint>

// QuantizedEmbedding FINAL: LDG.128 gather + warp-autonomous TMA bulk stores.
// Chosen for speed AND robustness: reads sleep on LDG scoreboards (no mbarrier
// spin loops that burn issue slots when TMA service is slow); the write stream
// uses cp.async.bulk (the single biggest lever: L2 38% vs 61%, ~-12us vs STG).
// Per warp: 2KB out slice double-buffered, wait_group 1; scales and indices
// prefetched; no CTA-wide barriers in the loop.

static constexpr int PACKED   = 2048;    // packed int32 per row
static constexpr int NGROUPS  = 128;
static constexpr int DIM      = 4096;
static constexpr int THREADS  = 256;     // thread t: packed [t*8, t*8+8) -> group t>>1
static constexpr int TOKS     = 4;       // tokens per CTA (grid 4096)
static constexpr int WARPS    = THREADS / 32;
static constexpr int SLICE_F  = DIM / WARPS;           // 512 floats = 2KB per warp slice
static constexpr int SLICE_B  = SLICE_F * 4;           // 2048 bytes
static constexpr int SMEM_BYTES = WARPS * 2 * SLICE_B; // 32KB

__device__ __forceinline__ float4 dq2(int a, int b, float s) {
    float4 r;
    r.x = (float)(a / 16 - 8) * s;       // trunc-toward-zero high nibble
    r.y = (float)((a & 15) - 8) * s;     // nonneg mod-16 low nibble
    r.z = (float)(b / 16 - 8) * s;
    r.w = (float)((b & 15) - 8) * s;
    return r;
}

__global__ void __launch_bounds__(THREADS)
qemb_kernel(const int* __restrict__ indices,
            const int* __restrict__ weight,
            const float* __restrict__ scales,
            float* __restrict__ out,
            int n_tokens)
{
    extern __shared__ float4 buf[];   // [WARPS][2][SLICE_F/4]
    int t    = threadIdx.x;
    int warp = t >> 5;
    int lane = t & 31;
    long base = (long)blockIdx.x * TOKS;   // 16384 = 4096*4, exact

    float4* wbuf = buf + (size_t)warp * 2 * (SLICE_F / 4);

    // all 4 token indices in one load
    int4 idx4 = __ldg(reinterpret_cast<const int4*>(indices + base));
    int idxs[TOKS] = { idx4.x, idx4.y, idx4.z, idx4.w };

    // prefetch token 0 weights and ALL 4 scales (independent LDGs, deep MLP)
    const int4* wr = reinterpret_cast<const int4*>(weight + (long)idxs[0] * PACKED) + t * 2;
    int4 w0 = __ldg(wr);
    int4 w1 = __ldg(wr + 1);
    float sc[TOKS];
    #pragma unroll
    for (int j = 0; j < TOKS; j++)
        sc[j] = __ldg(scales + (long)idxs[j] * NGROUPS + (t >> 1));

    #pragma unroll
    for (int i = 0; i < TOKS; i++) {
        int k = i & 1;

        // prefetch token i+1 weights (independent of everything below)
        int4 n0, n1;
        if (i + 1 < TOKS) {
            const int4* wr2 =
                reinterpret_cast<const int4*>(weight + (long)idxs[i + 1] * PACKED) + t * 2;
            n0 = __ldg(wr2);
            n1 = __ldg(wr2 + 1);
        }

        // out-buffer k reuse guard: its bulk store was committed at iter i-2
        if (i >= 2 && lane == 0)
            asm volatile("cp.async.bulk.wait_group %0;" :: "n"(1) : "memory");
        __syncwarp();

        // dequant straight into smem (lane writes 4 consecutive float4 = 64B)
        float s = sc[i];
        float4* bp = wbuf + (size_t)k * (SLICE_F / 4) + lane * 4;
        bp[0] = dq2(w0.x, w0.y, s);
        bp[1] = dq2(w0.z, w0.w, s);
        bp[2] = dq2(w1.x, w1.y, s);
        bp[3] = dq2(w1.z, w1.w, s);

        asm volatile("fence.proxy.async.shared::cta;" ::: "memory");
        __syncwarp();

        if (lane == 0) {
            uint32_t saddr = (uint32_t)__cvta_generic_to_shared(
                wbuf + (size_t)k * (SLICE_F / 4));
            void* g = (void*)(out + (base + i) * DIM + warp * SLICE_F);
            asm volatile("cp.async.bulk.global.shared::cta.bulk_group [%0], [%1], %2;"
                         :: "l"(g), "r"(saddr), "n"(SLICE_B) : "memory");
            asm volatile("cp.async.bulk.commit_group;" ::: "memory");
        }

        w0 = n0; w1 = n1;
    }

    // drain this warp's pending bulk stores before exit
    if (lane == 0)
        asm volatile("cp.async.bulk.wait_group 0;" ::: "memory");
}

extern "C" void kernel_launch(void* const* d_in, const int* in_sizes, int n_in,
                              void* d_out, int out_size)
{
    const int*   indices = (const int*)d_in[0];
    const int*   weight  = (const int*)d_in[1];
    const float* scales  = (const float*)d_in[2];
    float*       out     = (float*)d_out;

    int n_tokens = in_sizes[0];  // 16384

    cudaFuncSetAttribute(qemb_kernel,
                         cudaFuncAttributeMaxDynamicSharedMemorySize, SMEM_BYTES);
    cudaFuncSetAttribute(qemb_kernel,
                         cudaFuncAttributePreferredSharedMemoryCarveout, 100);

    int grid = n_tokens / TOKS;  // 4096
    qemb_kernel<<<grid, THREADS, SMEM_BYTES>>>(indices, weight, scales, out, n_tokens);
}